// round 13
// baseline (speedup 1.0000x reference)
#include <cuda_runtime.h>
#include <math.h>
#include <stdint.h>

#define NPIX    784
#define NPOS    676
#define NCH     8
#define NCLS    10
#define FLATK   5408
#define THREADS 128
#define IMGB    4
#define NSTEPS  6                 // ceil(676/128)
#define NCHUNK  (NSTEPS * NCH)    // 48 chunks: k = s*8 + c
#define RING    4
#define ROWB    512               // bytes per class-row slot (128 p * 4B)
#define CHUNKB  (NCLS * ROWB)     // 5120 B per chunk

// Tree max over the 9-pixel window (field F of float4), register-only.
#define FZ_FIELD(F)                                                        \
    ({                                                                     \
        float a0 = q[0].F + w[0];                                          \
        float a1 = q[1].F + w[1];                                          \
        float a2 = q[2].F + w[2];                                          \
        float a3 = q[3].F + w[3];                                          \
        float a4 = q[4].F + w[4];                                          \
        float a5 = q[5].F + w[5];                                          \
        float a6 = q[6].F + w[6];                                          \
        float a7 = q[7].F + w[7];                                          \
        float a8 = q[8].F + w[8];                                          \
        float b0 = fmaxf(a0, a1);                                          \
        float b1 = fmaxf(a2, a3);                                          \
        float b2 = fmaxf(a4, a5);                                          \
        float b3 = fmaxf(a6, a7);                                          \
        fmaxf(fmaxf(fmaxf(fmaxf(b0, b1), fmaxf(b2, b3)), a8), 0.0f);       \
    })

__device__ __forceinline__ void mbar_init(uint32_t a, uint32_t cnt) {
    asm volatile("mbarrier.init.shared.b64 [%0], %1;" :: "r"(a), "r"(cnt) : "memory");
}
__device__ __forceinline__ void mbar_arrive(uint32_t a) {
    asm volatile("mbarrier.arrive.shared.b64 _, [%0];" :: "r"(a) : "memory");
}
__device__ __forceinline__ void mbar_expect_tx(uint32_t a, uint32_t bytes) {
    asm volatile("mbarrier.arrive.expect_tx.shared.b64 _, [%0], %1;"
                 :: "r"(a), "r"(bytes) : "memory");
}
__device__ __forceinline__ void mbar_wait(uint32_t a, uint32_t parity) {
    asm volatile(
        "{\n\t.reg .pred P;\n\t"
        "WL_%=:\n\t"
        "mbarrier.try_wait.parity.acquire.cta.shared::cta.b64 P, [%0], %1, 0x989680;\n\t"
        "@P bra.uni WD_%=;\n\t"
        "bra.uni WL_%=;\n\t"
        "WD_%=:\n\t}"
        :: "r"(a), "r"(parity) : "memory");
}
__device__ __forceinline__ void bulk_cp(uint32_t dst, const float* src,
                                        uint32_t bytes, uint32_t mbar) {
    asm volatile(
        "cp.async.bulk.shared::cta.global.mbarrier::complete_tx::bytes "
        "[%0], [%1], %2, [%3];"
        :: "r"(dst), "l"(src), "r"(bytes), "r"(mbar) : "memory");
}

// Producer-side: stage chunk kk (s = kk>>3, c = kk&7) into slot ringb.
__device__ __forceinline__ void stage_chunk(uint32_t ringb, uint32_t fullb,
                                            const float* __restrict__ wd, int kk) {
    const int s   = kk >> 3;
    const int c   = kk & 7;
    const uint32_t len = (s < 5) ? 512u : 144u;   // tail step: 36 p * 4B
    mbar_expect_tx(fullb, len * NCLS);
    const float* src = wd + c * NPOS + s * 128;
    #pragma unroll
    for (int o = 0; o < NCLS; o++)
        bulk_cp(ringb + o * ROWB, src + o * FLATK, len, fullb);
}

__global__ __launch_bounds__(THREADS, 4)
void fused_afrnn_kernel(const float* __restrict__ x,
                        const float* __restrict__ wfuzzy,
                        const float* __restrict__ wdense,
                        float* __restrict__ out)
{
    __shared__ float4 sx4[NPIX];                         // 12.5 KB
    __shared__ float4 swf[NCH * 3];                      // fuzzy (w-1)
    __shared__ __align__(16) char ring[RING * CHUNKB];   // 20 KB weight ring
    __shared__ __align__(8)  unsigned long long mbar[2 * RING]; // full[4], empty[4]
    __shared__ float  red[4][IMGB * NCLS];
    __shared__ float  tot[IMGB * NCLS];

    const int tid  = threadIdx.x;
    const int lane = tid & 31;
    const int wid  = tid >> 5;
    const int img0 = blockIdx.x * IMGB;

    const uint32_t ring0 = (uint32_t)__cvta_generic_to_shared(ring);
    const uint32_t mb0   = (uint32_t)__cvta_generic_to_shared(mbar);
    // full[b] at mb0 + b*8 ; empty[b] at mb0 + 32 + b*8

    if (tid == 0) {
        #pragma unroll
        for (int b = 0; b < RING; b++) {
            mbar_init(mb0 + b * 8, 1);            // full: producer expect_tx arrive
            mbar_init(mb0 + 32 + b * 8, THREADS); // empty: all threads arrive
        }
        asm volatile("fence.proxy.async.shared::cta;" ::: "memory");
    }
    __syncthreads();

    // Prologue: stage chunks 0..3 (ring full depth)
    if (tid == 0) {
        #pragma unroll
        for (int kk = 0; kk < RING; kk++)
            stage_chunk(ring0 + kk * CHUNKB, mb0 + kk * 8, wdense, kk);
    }

    // Stage images (interleaved) + fuzzy weights
    {
        float* sxs = (float*)sx4;
        const float* x0 = x + (size_t)img0 * NPIX;
        for (int idx = tid; idx < IMGB * NPIX; idx += THREADS) {
            int im  = idx / NPIX;
            int pix = idx - im * NPIX;
            sxs[pix * 4 + im] = x0[idx];
        }
        if (tid < NCH * 3) {
            int c = tid / 3, j = tid - c * 3;
            float v[4];
            #pragma unroll
            for (int kq = 0; kq < 4; kq++) {
                int o = j * 4 + kq;
                v[kq] = (o < 9) ? (wfuzzy[c * 9 + o] - 1.0f) : 0.0f;
            }
            swf[tid] = make_float4(v[0], v[1], v[2], v[3]);
        }
    }
    __syncthreads();

    float acc[IMGB][NCLS];
    #pragma unroll
    for (int im = 0; im < IMGB; im++)
        #pragma unroll
        for (int o = 0; o < NCLS; o++) acc[im][o] = 0.0f;

    int k = 0;   // chunk index = s*8 + c

    for (int s = 0; s < NSTEPS; s++) {
        const int p     = tid + s * THREADS;
        const bool valid = (p < NPOS);
        const int pc    = valid ? p : NPOS - 1;
        const int i     = pc / 26;
        const int j     = pc - i * 26;
        const int base  = i * 28 + j;

        // 3x3 window x 4 images: 9 LDS.128
        float4 q[9];
        #pragma unroll
        for (int r = 0; r < 3; r++)
            #pragma unroll
            for (int cc = 0; cc < 3; cc++)
                q[r * 3 + cc] = sx4[base + r * 28 + cc];

        #pragma unroll
        for (int c = 0; c < NCH; c++) {
            const int b        = k & 3;
            const uint32_t par = (uint32_t)((k >> 2) & 1);

            // consume: wait chunk staged, read 10 conflict-free LDS.32
            mbar_wait(mb0 + b * 8, par);
            float wv[NCLS];
            {
                const uint32_t ra = ring0 + b * CHUNKB + ((uint32_t)tid << 2);
                #pragma unroll
                for (int o = 0; o < NCLS; o++)
                    asm volatile("ld.shared.f32 %0, [%1];"
                                 : "=f"(wv[o]) : "r"(ra + o * ROWB));
            }

            if (valid) {
                const float4 wA = swf[c * 3 + 0];
                const float4 wB = swf[c * 3 + 1];
                const float4 wC = swf[c * 3 + 2];
                const float w[9] = { wA.x, wA.y, wA.z, wA.w,
                                     wB.x, wB.y, wB.z, wB.w, wC.x };

                const float fz0 = FZ_FIELD(x);
                const float fz1 = FZ_FIELD(y);
                const float fz2 = FZ_FIELD(z);
                const float fz3 = FZ_FIELD(w);

                #pragma unroll
                for (int o = 0; o < NCLS; o++) {
                    acc[0][o] = fmaf(fz0, wv[o], acc[0][o]);
                    acc[1][o] = fmaf(fz1, wv[o], acc[1][o]);
                    acc[2][o] = fmaf(fz2, wv[o], acc[2][o]);
                    acc[3][o] = fmaf(fz3, wv[o], acc[3][o]);
                }
            }

            // release the slot (after wv fully consumed by the FFMAs above)
            mbar_arrive(mb0 + 32 + b * 8);

            // producer: refill this slot with chunk k+4 once all 128 released it
            if (tid == 0 && k + RING < NCHUNK) {
                mbar_wait(mb0 + 32 + b * 8, par);
                stage_chunk(ring0 + b * CHUNKB, mb0 + b * 8, wdense, k + RING);
            }
            k++;
        }
    }

    // ---- reduce partial logits across the block ----
    #pragma unroll
    for (int im = 0; im < IMGB; im++) {
        #pragma unroll
        for (int o = 0; o < NCLS; o++) {
            float t = acc[im][o];
            t += __shfl_down_sync(0xffffffffu, t, 16);
            t += __shfl_down_sync(0xffffffffu, t, 8);
            t += __shfl_down_sync(0xffffffffu, t, 4);
            t += __shfl_down_sync(0xffffffffu, t, 2);
            t += __shfl_down_sync(0xffffffffu, t, 1);
            if (lane == 0) red[wid][im * NCLS + o] = t;
        }
    }
    __syncthreads();

    if (tid < IMGB * NCLS)
        tot[tid] = red[0][tid] + red[1][tid] + red[2][tid] + red[3][tid];
    __syncthreads();

    // ---- log_softmax (1 thread per image) ----
    if (tid < IMGB) {
        float l[NCLS];
        float mx = -1e30f;
        #pragma unroll
        for (int o = 0; o < NCLS; o++) {
            l[o] = tot[tid * NCLS + o];
            mx = fmaxf(mx, l[o]);
        }
        float sum = 0.0f;
        #pragma unroll
        for (int o = 0; o < NCLS; o++) sum += expf(l[o] - mx);
        const float lse = mx + logf(sum);
        float* op = out + (size_t)(img0 + tid) * NCLS;
        #pragma unroll
        for (int o = 0; o < NCLS; o++) op[o] = l[o] - lse;
    }
}

extern "C" void kernel_launch(void* const* d_in, const int* in_sizes, int n_in,
                              void* d_out, int out_size)
{
    const float* x  = (const float*)d_in[0];   // (4096,1,28,28) fp32
    const float* wf = (const float*)d_in[1];   // (8,1,3,3)      fp32
    const float* wd = (const float*)d_in[2];   // (10,5408)      fp32
    float* out = (float*)d_out;                // (4096,10)      fp32

    const int nimg = in_sizes[0] / NPIX;       // 4096
    fused_afrnn_kernel<<<nimg / IMGB, THREADS>>>(x, wf, wd, out);
}

// round 14
// speedup vs baseline: 2.0460x; 2.0460x over previous
#include <cuda_runtime.h>
#include <math.h>

#define NPIX   784
#define NPOS   676
#define NCH    8
#define NCLS   10
#define FLATK  5408
#define THREADS 256
#define GTH    128          // threads per warp-group
#define IMGB   8            // images per block (4 per warp-group)
#define GIMG   4            // images per warp-group

__global__ __launch_bounds__(THREADS, 2)
void fused_afrnn_kernel(const float* __restrict__ x,
                        const float* __restrict__ wfuzzy,
                        const float* __restrict__ wdense,
                        float* __restrict__ out)
{
    __shared__ float sx[IMGB * NPIX];       // 8 images, scalar layout, 25 KB
    __shared__ float swf[NCH * 9];          // fuzzy weights, -1 folded
    __shared__ float red[8][GIMG * NCLS];   // per-warp partials
    __shared__ float tot[IMGB * NCLS];

    const int tid  = threadIdx.x;
    const int img0 = blockIdx.x * IMGB;

    // ---- stage 8 images (float4 vectorized) + fuzzy weights ----
    {
        const float4* xin = (const float4*)(x + (size_t)img0 * NPIX);
        float4* sx4 = (float4*)sx;
        for (int i = tid; i < IMGB * (NPIX / 4); i += THREADS)
            sx4[i] = xin[i];
        if (tid < NCH * 9) swf[tid] = wfuzzy[tid] - 1.0f;   // fold the -1
    }
    __syncthreads();

    // warp-group split: warps 0-3 -> images 0-3, warps 4-7 -> images 4-7.
    // Both groups iterate the SAME p in the SAME order -> every dense-weight
    // line is touched by 8 warps inside one p-step window (L1 sharing).
    const int g   = tid >> 7;           // group 0/1
    const int gt  = tid & 127;          // thread-in-group
    const float* sxg = sx + g * GIMG * NPIX;

    float acc[GIMG][NCLS];
    #pragma unroll
    for (int im = 0; im < GIMG; im++)
        #pragma unroll
        for (int o = 0; o < NCLS; o++) acc[im][o] = 0.0f;

    for (int p = gt; p < NPOS; p += GTH) {
        const int i    = p / 26;
        const int j    = p - i * 26;
        const int base = i * 28 + j;

        // 9-pixel window for each of the group's 4 images -> registers
        float px[GIMG][9];
        #pragma unroll
        for (int im = 0; im < GIMG; im++) {
            #pragma unroll
            for (int r = 0; r < 3; r++)
                #pragma unroll
                for (int cc = 0; cc < 3; cc++)
                    px[im][r * 3 + cc] = sxg[im * NPIX + base + r * 28 + cc];
        }

        #pragma unroll
        for (int c = 0; c < NCH; c++) {
            float wr[9];
            #pragma unroll
            for (int k = 0; k < 9; k++) wr[k] = swf[c * 9 + k];  // broadcast

            // fz = relu(max_k(px + (w-1))) for each image (linear chain, as R1)
            float fz[GIMG];
            #pragma unroll
            for (int im = 0; im < GIMG; im++) {
                float m = px[im][0] + wr[0];
                #pragma unroll
                for (int k = 1; k < 9; k++)
                    m = fmaxf(m, px[im][k] + wr[k]);
                fz[im] = fmaxf(m, 0.0f);
            }

            // dense partial: 10 independent coalesced scalar LDG
            const float* wcol = wdense + c * NPOS + p;
            #pragma unroll
            for (int o = 0; o < NCLS; o++) {
                const float wv = __ldg(wcol + o * FLATK);
                #pragma unroll
                for (int im = 0; im < GIMG; im++)
                    acc[im][o] = fmaf(fz[im], wv, acc[im][o]);
            }
        }
    }

    // ---- reduce partial logits: warp shuffle -> smem -> totals ----
    const int lane = tid & 31;
    const int wid  = tid >> 5;          // 0..7
    #pragma unroll
    for (int im = 0; im < GIMG; im++) {
        #pragma unroll
        for (int o = 0; o < NCLS; o++) {
            float v = acc[im][o];
            v += __shfl_down_sync(0xffffffffu, v, 16);
            v += __shfl_down_sync(0xffffffffu, v, 8);
            v += __shfl_down_sync(0xffffffffu, v, 4);
            v += __shfl_down_sync(0xffffffffu, v, 2);
            v += __shfl_down_sync(0xffffffffu, v, 1);
            if (lane == 0) red[wid][im * NCLS + o] = v;
        }
    }
    __syncthreads();

    // tot[(g*4+im)*10+o] = sum over the group's 4 warps
    if (tid < IMGB * NCLS) {            // 80 threads
        const int g2  = tid / (GIMG * NCLS);
        const int idx = tid - g2 * (GIMG * NCLS);
        tot[tid] = red[4 * g2 + 0][idx] + red[4 * g2 + 1][idx] +
                   red[4 * g2 + 2][idx] + red[4 * g2 + 3][idx];
    }
    __syncthreads();

    // ---- log_softmax per image (1 thread per image) ----
    if (tid < IMGB) {
        float l[NCLS];
        float mx = -1e30f;
        #pragma unroll
        for (int o = 0; o < NCLS; o++) {
            l[o] = tot[tid * NCLS + o];
            mx = fmaxf(mx, l[o]);
        }
        float s = 0.0f;
        #pragma unroll
        for (int o = 0; o < NCLS; o++) s += expf(l[o] - mx);
        const float lse = mx + logf(s);
        float* op = out + (size_t)(img0 + tid) * NCLS;
        #pragma unroll
        for (int o = 0; o < NCLS; o++) op[o] = l[o] - lse;
    }
}

extern "C" void kernel_launch(void* const* d_in, const int* in_sizes, int n_in,
                              void* d_out, int out_size)
{
    const float* x  = (const float*)d_in[0];   // (4096,1,28,28) fp32
    const float* wf = (const float*)d_in[1];   // (8,1,3,3)      fp32
    const float* wd = (const float*)d_in[2];   // (10,5408)      fp32
    float* out = (float*)d_out;                // (4096,10)      fp32

    const int nimg = in_sizes[0] / NPIX;       // 4096
    fused_afrnn_kernel<<<nimg / IMGB, THREADS>>>(x, wf, wd, out);
}

// round 15
// speedup vs baseline: 2.2710x; 1.1100x over previous
#include <cuda_runtime.h>
#include <math.h>

// Problem constants
#define NPIX   784      // 28*28
#define NPOS   676      // 26*26
#define NCH    8
#define NCLS   10
#define FLATK  5408
#define IMGB   4        // images per block (register blocking factor)
#define THREADS 128
#define NWARP  4

__global__ __launch_bounds__(THREADS)
void fused_afrnn_kernel(const float* __restrict__ x,
                        const float* __restrict__ wfuzzy,
                        const float* __restrict__ wdense,
                        float* __restrict__ out)
{
    __shared__ float sx[IMGB * NPIX];       // 4 images, 12.5 KB
    __shared__ float swf[NCH * 9];          // fuzzy weights, -1 pre-folded
    __shared__ float red[NWARP][IMGB * NCLS];
    __shared__ float tot[IMGB * NCLS];

    const int tid  = threadIdx.x;
    const int img0 = blockIdx.x * IMGB;

    // ---- stage 4 images (float4 vectorized) + fuzzy weights ----
    {
        const float4* xin = (const float4*)(x + (size_t)img0 * NPIX);
        float4* sx4 = (float4*)sx;
        #pragma unroll
        for (int i = tid; i < IMGB * (NPIX / 4); i += THREADS)
            sx4[i] = xin[i];
        if (tid < NCH * 9) swf[tid] = wfuzzy[tid] - 1.0f;   // fold relu's -1
    }
    __syncthreads();

    // ---- per-thread partial logits for 4 images ----
    float acc[IMGB][NCLS];
    #pragma unroll
    for (int im = 0; im < IMGB; im++)
        #pragma unroll
        for (int o = 0; o < NCLS; o++) acc[im][o] = 0.0f;

    for (int p = tid; p < NPOS; p += THREADS) {
        const int i    = p / 26;
        const int j    = p - i * 26;
        const int base = i * 28 + j;

        // 9-pixel window for each of the 4 images -> registers
        float px[IMGB][9];
        #pragma unroll
        for (int im = 0; im < IMGB; im++) {
            #pragma unroll
            for (int r = 0; r < 3; r++)
                #pragma unroll
                for (int cc = 0; cc < 3; cc++)
                    px[im][r * 3 + cc] = sx[im * NPIX + base + r * 28 + cc];
        }

        #pragma unroll
        for (int c = 0; c < NCH; c++) {
            float wr[9];
            #pragma unroll
            for (int k = 0; k < 9; k++) wr[k] = swf[c * 9 + k];   // smem broadcast

            // fz = relu(max_k(px + (w-1))) for each image
            float fz[IMGB];
            #pragma unroll
            for (int im = 0; im < IMGB; im++) {
                float m = px[im][0] + wr[0];
                #pragma unroll
                for (int k = 1; k < 9; k++)
                    m = fmaxf(m, px[im][k] + wr[k]);
                fz[im] = fmaxf(m, 0.0f);
            }

            // dense partial: one w load serves 4 images (register blocking)
            const float* wcol = wdense + c * NPOS + p;
            #pragma unroll
            for (int o = 0; o < NCLS; o++) {
                const float wv = __ldg(wcol + o * FLATK);
                #pragma unroll
                for (int im = 0; im < IMGB; im++)
                    acc[im][o] = fmaf(fz[im], wv, acc[im][o]);
            }
        }
    }

    // ---- reduce partial logits: warp shuffle -> smem -> totals ----
    const int lane = tid & 31;
    const int wid  = tid >> 5;
    #pragma unroll
    for (int im = 0; im < IMGB; im++) {
        #pragma unroll
        for (int o = 0; o < NCLS; o++) {
            float v = acc[im][o];
            v += __shfl_down_sync(0xffffffffu, v, 16);
            v += __shfl_down_sync(0xffffffffu, v, 8);
            v += __shfl_down_sync(0xffffffffu, v, 4);
            v += __shfl_down_sync(0xffffffffu, v, 2);
            v += __shfl_down_sync(0xffffffffu, v, 1);
            if (lane == 0) red[wid][im * NCLS + o] = v;
        }
    }
    __syncthreads();

    if (tid < IMGB * NCLS) {
        tot[tid] = red[0][tid] + red[1][tid] + red[2][tid] + red[3][tid];
    }
    __syncthreads();

    // ---- log_softmax per image (1 thread per image; trivially small) ----
    if (tid < IMGB) {
        float l[NCLS];
        float mx = -1e30f;
        #pragma unroll
        for (int o = 0; o < NCLS; o++) {
            l[o] = tot[tid * NCLS + o];
            mx = fmaxf(mx, l[o]);
        }
        float s = 0.0f;
        #pragma unroll
        for (int o = 0; o < NCLS; o++) s += expf(l[o] - mx);
        const float lse = mx + logf(s);
        float* op = out + (size_t)(img0 + tid) * NCLS;
        #pragma unroll
        for (int o = 0; o < NCLS; o++) op[o] = l[o] - lse;
    }
}

extern "C" void kernel_launch(void* const* d_in, const int* in_sizes, int n_in,
                              void* d_out, int out_size)
{
    const float* x  = (const float*)d_in[0];   // (4096,1,28,28) fp32
    const float* wf = (const float*)d_in[1];   // (8,1,3,3)      fp32
    const float* wd = (const float*)d_in[2];   // (10,5408)      fp32
    float* out = (float*)d_out;                // (4096,10)      fp32

    const int nimg = in_sizes[0] / NPIX;       // 4096
    fused_afrnn_kernel<<<nimg / IMGB, THREADS>>>(x, wf, wd, out);
}

// round 16
// speedup vs baseline: 2.2749x; 1.0017x over previous
#include <cuda_runtime.h>
#include <math.h>

// Problem constants
#define NPIX   784      // 28*28
#define NPOS   676      // 26*26
#define NCH    8
#define NCLS   10
#define FLATK  5408
#define IMGB   4        // images per block (register blocking factor)
#define THREADS 128
#define NWARP  4

__global__ __launch_bounds__(THREADS)
void fused_afrnn_kernel(const float* __restrict__ x,
                        const float* __restrict__ wfuzzy,
                        const float* __restrict__ wdense,
                        float* __restrict__ out)
{
    __shared__ float sx[IMGB * NPIX];       // 4 images, 12.5 KB
    __shared__ float swf[NCH * 9];          // fuzzy weights, -1 pre-folded
    __shared__ float red[NWARP][IMGB * NCLS];
    __shared__ float tot[IMGB * NCLS];

    const int tid  = threadIdx.x;
    const int lane = tid & 31;
    const int wid  = tid >> 5;
    const int img0 = blockIdx.x * IMGB;

    // ---- stage 4 images (float4 vectorized) + fuzzy weights ----
    {
        const float4* xin = (const float4*)(x + (size_t)img0 * NPIX);
        float4* sx4 = (float4*)sx;
        #pragma unroll
        for (int i = tid; i < IMGB * (NPIX / 4); i += THREADS)
            sx4[i] = xin[i];
        if (tid < NCH * 9) swf[tid] = wfuzzy[tid] - 1.0f;   // fold relu's -1
    }
    __syncthreads();

    // ---- per-thread partial logits for 4 images ----
    float acc[IMGB][NCLS];
    #pragma unroll
    for (int im = 0; im < IMGB; im++)
        #pragma unroll
        for (int o = 0; o < NCLS; o++) acc[im][o] = 0.0f;

    // Block-rotated warp-work assignment: the tail iteration (p >= 640,
    // 36 positions) always lands on effective-chunk e in {0,1}.  Rotating
    // e by blockIdx.x spreads 6-iteration warps evenly across the four
    // SMSPs (each SMSP hosts one warp from each of ~4 consecutive blocks),
    // balancing per-SMSP issued work at 6+6+5+5 = 22 warp-iters instead of
    // SMSP0/1 = 24, SMSP2/3 = 20.  Lane-contiguity (coalescing) unchanged.
    const int e     = (wid + (int)blockIdx.x) & 3;
    const int pbase = e * 32 + lane;

    for (int p = pbase; p < NPOS; p += THREADS) {
        const int i    = p / 26;
        const int j    = p - i * 26;
        const int base = i * 28 + j;

        // 9-pixel window for each of the 4 images -> registers
        float px[IMGB][9];
        #pragma unroll
        for (int im = 0; im < IMGB; im++) {
            #pragma unroll
            for (int r = 0; r < 3; r++)
                #pragma unroll
                for (int cc = 0; cc < 3; cc++)
                    px[im][r * 3 + cc] = sx[im * NPIX + base + r * 28 + cc];
        }

        #pragma unroll
        for (int c = 0; c < NCH; c++) {
            float wr[9];
            #pragma unroll
            for (int k = 0; k < 9; k++) wr[k] = swf[c * 9 + k];   // smem broadcast

            // fz = relu(max_k(px + (w-1))) for each image
            float fz[IMGB];
            #pragma unroll
            for (int im = 0; im < IMGB; im++) {
                float m = px[im][0] + wr[0];
                #pragma unroll
                for (int k = 1; k < 9; k++)
                    m = fmaxf(m, px[im][k] + wr[k]);
                fz[im] = fmaxf(m, 0.0f);
            }

            // dense partial: one w load serves 4 images (register blocking)
            const float* wcol = wdense + c * NPOS + p;
            #pragma unroll
            for (int o = 0; o < NCLS; o++) {
                const float wv = __ldg(wcol + o * FLATK);
                #pragma unroll
                for (int im = 0; im < IMGB; im++)
                    acc[im][o] = fmaf(fz[im], wv, acc[im][o]);
            }
        }
    }

    // ---- reduce partial logits: warp shuffle -> smem -> totals ----
    #pragma unroll
    for (int im = 0; im < IMGB; im++) {
        #pragma unroll
        for (int o = 0; o < NCLS; o++) {
            float v = acc[im][o];
            v += __shfl_down_sync(0xffffffffu, v, 16);
            v += __shfl_down_sync(0xffffffffu, v, 8);
            v += __shfl_down_sync(0xffffffffu, v, 4);
            v += __shfl_down_sync(0xffffffffu, v, 2);
            v += __shfl_down_sync(0xffffffffu, v, 1);
            if (lane == 0) red[wid][im * NCLS + o] = v;
        }
    }
    __syncthreads();

    if (tid < IMGB * NCLS) {
        tot[tid] = red[0][tid] + red[1][tid] + red[2][tid] + red[3][tid];
    }
    __syncthreads();

    // ---- log_softmax per image (1 thread per image; trivially small) ----
    if (tid < IMGB) {
        float l[NCLS];
        float mx = -1e30f;
        #pragma unroll
        for (int o = 0; o < NCLS; o++) {
            l[o] = tot[tid * NCLS + o];
            mx = fmaxf(mx, l[o]);
        }
        float s = 0.0f;
        #pragma unroll
        for (int o = 0; o < NCLS; o++) s += expf(l[o] - mx);
        const float lse = mx + logf(s);
        float* op = out + (size_t)(img0 + tid) * NCLS;
        #pragma unroll
        for (int o = 0; o < NCLS; o++) op[o] = l[o] - lse;
    }
}

extern "C" void kernel_launch(void* const* d_in, const int* in_sizes, int n_in,
                              void* d_out, int out_size)
{
    const float* x  = (const float*)d_in[0];   // (4096,1,28,28) fp32
    const float* wf = (const float*)d_in[1];   // (8,1,3,3)      fp32
    const float* wd = (const float*)d_in[2];   // (10,5408)      fp32
    float* out = (float*)d_out;                // (4096,10)      fp32

    const int nimg = in_sizes[0] / NPIX;       // 4096
    fused_afrnn_kernel<<<nimg / IMGB, THREADS>>>(x, wf, wd, out);
}